// round 12
// baseline (speedup 1.0000x reference)
#include <cuda_runtime.h>
#include <cstdint>

// Screen / tiling constants (W=1280, H=720 are exact multiples of L=16)
#define W_SCREEN 1280.0f
#define H_SCREEN 720.0f
#define NBW      80
#define NBH      45
#define N_POINTS 32768
#define ROWS_PER_CTA 9     // 45 = 5 * 9
#define BANDS     5

// Per-point tile intervals packed into one uint32:
//   byte0 = a   (first valid yi)   byte1 = n  (y-interval length)
//   byte2 = ax0 (first valid xi)   byte3 = nx (last-first xi)
__device__ __align__(16) unsigned g_packed[N_POINTS];

// Kernel 1 (tiny): per-point AABB -> packed tile intervals.
// Mirrors reference create_tiles; with right=left+16, bottom=top+16 exact and
// xmax>xmin, ymax>ymin guaranteed (radius >= 1), the overlap test is the
// separable test  (unsigned)(xi-ax0) <= nx  &&  (unsigned)(yi-a) < n.
__global__ void prep_kernel(const float* __restrict__ pos2d,
                            const float* __restrict__ radius) {
    int i = blockIdx.x * blockDim.x + threadIdx.x;
    if (i < N_POINTS) {
        float x = pos2d[2 * i];
        float y = pos2d[2 * i + 1];
        float r = radius[i];
        int xmin = (int)fminf(fmaxf(x - r, 0.0f), W_SCREEN);
        int xmax = (int)fminf(fmaxf(x + r, 0.0f), W_SCREEN);
        int ymin = (int)fminf(fmaxf(y - r, 0.0f), H_SCREEN);
        int ymax = (int)fminf(fmaxf(y + r, 0.0f), H_SCREEN);

        unsigned a   = (unsigned)(ymin >> 4);
        unsigned n   = (unsigned)(((ymax - 1) >> 4) + 1) - a;
        unsigned ax0 = (unsigned)(xmin >> 4);
        unsigned nx  = (unsigned)((xmax - 1) >> 4) - ax0;

        g_packed[i] = a | (n << 8) | (ax0 << 16) | (nx << 24);
    }
    // Allow the dependent mask grid to finish launching as soon as our
    // packed table is written (all stores above precede the trigger).
    cudaTriggerProgrammaticLaunchCompletion();
}

// Kernel 2: one block per (512-point chunk, xi column, 9-row band); each
// thread owns 4 consecutive points. Launched with PDL: index math happens
// before cudaGridDependencySynchronize(), so grid launch/ramp overlaps
// prep_kernel's execution. Then one LDG.128 of packed intervals + byte
// extraction, and the band sweep emits one float4 (STG.128) per row.
__global__ __launch_bounds__(128) void mask_kernel(float* __restrict__ out) {
    int g  = blockIdx.x * 128 + threadIdx.x;   // 4-point group, 0..8191
    int xi = blockIdx.y;                       // 0..79
    int y0 = blockIdx.z * ROWS_PER_CTA;        // 0, 9, 18, 27, 36

    float* optr = out + ((size_t)xi * NBH + y0) * N_POINTS + (size_t)g * 4;

    // Wait for prep_kernel's packed table (PDL dependency).
    cudaGridDependencySynchronize();

    uint4 pk = reinterpret_cast<const uint4*>(g_packed)[g];

    unsigned a[4], n[4];
    {
        unsigned w[4] = {pk.x, pk.y, pk.z, pk.w};
#pragma unroll
        for (int j = 0; j < 4; j++) {
            unsigned aj  = w[j] & 0xFFu;
            unsigned nj  = (w[j] >> 8) & 0xFFu;
            unsigned ax0 = (w[j] >> 16) & 0xFFu;
            unsigned nx  = w[j] >> 24;
            a[j] = aj;
            n[j] = ((unsigned)(xi - ax0) <= nx) ? nj : 0u;  // fold x-validity
        }
    }

#pragma unroll
    for (int k = 0; k < ROWS_PER_CTA; k++) {
        int yi = y0 + k;
        float4 v;
        v.x = ((unsigned)(yi - a[0]) < n[0]) ? 1.0f : 0.0f;
        v.y = ((unsigned)(yi - a[1]) < n[1]) ? 1.0f : 0.0f;
        v.z = ((unsigned)(yi - a[2]) < n[2]) ? 1.0f : 0.0f;
        v.w = ((unsigned)(yi - a[3]) < n[3]) ? 1.0f : 0.0f;
        *reinterpret_cast<float4*>(optr) = v;
        optr += N_POINTS;
    }
}

extern "C" void kernel_launch(void* const* d_in, const int* in_sizes, int n_in,
                              void* d_out, int out_size) {
    const float* pos2d  = (const float*)d_in[0];   // [32768, 2] float32
    const float* radius = (const float*)d_in[1];   // [32768]    float32
    float* out          = (float*)d_out;           // [3600, 32768] float32

    prep_kernel<<<128, 256>>>(pos2d, radius);

    cudaLaunchConfig_t cfg = {};
    cfg.gridDim  = dim3(64, NBW, BANDS);           // 64 chunks x 80 xi x 5 bands
    cfg.blockDim = dim3(128, 1, 1);
    cudaLaunchAttribute attrs[1];
    attrs[0].id = cudaLaunchAttributeProgrammaticStreamSerialization;
    attrs[0].val.programmaticStreamSerializationAllowed = 1;
    cfg.attrs    = attrs;
    cfg.numAttrs = 1;
    cudaLaunchKernelEx(&cfg, mask_kernel, out);
}